// round 12
// baseline (speedup 1.0000x reference)
#include <cuda_runtime.h>
#include <cuda_bf16.h>
#include <cfloat>
#include <math.h>
#include <limits.h>

#define NN 200000
#define EE 3200000
#define BB 2000
#define NPG 100
#define KK 60
#define DD 97
#define NBLK 1184
#define AGRID 1184
#define TG 4
#define FULL 0xffffffffu

// ---------------- device scratch ----------------
__device__ float g_deg[NN];          // edge-weight sum only; reset in k_scan
__device__ float g_dis[NN];
__device__ int   g_cnt[NN];          // zero-init; reset in k_scan
__device__ int   g_off[NN + 1];
__device__ int   g_cur[NN];
__device__ unsigned long long g_state[256];  // lookback; reset in k_fill
__device__ int2  g_csr[EE];          // .x = src, .y = norm bits
__device__ int   g_eid[EE];
__device__ float g_x [NN * 32];
__device__ float g_y [NN * 32];
__device__ float g_h1[NN * 32];
__device__ float g_h2[NN * 32];
__device__ float g_h3[NN * 32];
__device__ float g_s [NN];
__device__ float g_h4[NN];

// ---------------- launch 0: mm0 (node blocks, float4 subgroup) + hist (edge blocks) ----------------
__global__ void k_head(const int* __restrict__ w, const int* __restrict__ z1,
                       const int* __restrict__ z2,
                       const float* __restrict__ emb_w, const float* __restrict__ emb_z1,
                       const float* __restrict__ emb_z2, const float* __restrict__ W0,
                       const int* __restrict__ ei, const float* __restrict__ ew) {
    if (blockIdx.x < NBLK) {
        __shared__ float Ws[96 * 32];
        for (int i = threadIdx.x; i < 96 * 32; i += blockDim.x) Ws[i] = W0[i];
        __syncthreads();
        int lane = threadIdx.x & 31;
        int sl = lane & 7, sg = lane >> 3;
        int warp = (blockIdx.x * blockDim.x + threadIdx.x) >> 5;
        const int nwarps = NBLK * 8;
        for (int n4 = warp * 4; n4 < NN; n4 += nwarps * 4) {
            int n = n4 + sg;
            const float4 r0 = *reinterpret_cast<const float4*>(emb_w  + w [n] * 32 + sl * 4);
            const float4 r1 = *reinterpret_cast<const float4*>(emb_z1 + z1[n] * 32 + sl * 4);
            const float4 r2 = *reinterpret_cast<const float4*>(emb_z2 + z2[n] * 32 + sl * 4);
            float4 acc = make_float4(0.f, 0.f, 0.f, 0.f);
#pragma unroll
            for (int k = 0; k < 32; k++) {
                float yk;
                if      ((k & 3) == 0) yk = r0.x;
                else if ((k & 3) == 1) yk = r0.y;
                else if ((k & 3) == 2) yk = r0.z;
                else                   yk = r0.w;
                yk = __shfl_sync(FULL, yk, (sg << 3) + (k >> 2));
                const float4 wk = *reinterpret_cast<const float4*>(Ws + k * 32 + sl * 4);
                acc.x += yk * wk.x; acc.y += yk * wk.y; acc.z += yk * wk.z; acc.w += yk * wk.w;
            }
#pragma unroll
            for (int k = 0; k < 32; k++) {
                float yk;
                if      ((k & 3) == 0) yk = r1.x;
                else if ((k & 3) == 1) yk = r1.y;
                else if ((k & 3) == 2) yk = r1.z;
                else                   yk = r1.w;
                yk = __shfl_sync(FULL, yk, (sg << 3) + (k >> 2));
                const float4 wk = *reinterpret_cast<const float4*>(Ws + (32 + k) * 32 + sl * 4);
                acc.x += yk * wk.x; acc.y += yk * wk.y; acc.z += yk * wk.z; acc.w += yk * wk.w;
            }
#pragma unroll
            for (int k = 0; k < 32; k++) {
                float yk;
                if      ((k & 3) == 0) yk = r2.x;
                else if ((k & 3) == 1) yk = r2.y;
                else if ((k & 3) == 2) yk = r2.z;
                else                   yk = r2.w;
                yk = __shfl_sync(FULL, yk, (sg << 3) + (k >> 2));
                const float4 wk = *reinterpret_cast<const float4*>(Ws + (64 + k) * 32 + sl * 4);
                acc.x += yk * wk.x; acc.y += yk * wk.y; acc.z += yk * wk.z; acc.w += yk * wk.w;
            }
            *reinterpret_cast<float4*>(g_x + n * 32 + sl * 4) = acc;
        }
    } else {
        int tid = (blockIdx.x - NBLK) * blockDim.x + threadIdx.x;
        const int nthr = NBLK * 256;
        for (int e = tid; e < EE; e += nthr) {
            int dst = ei[EE + e];
            atomicAdd(&g_deg[dst], ew[e]);
            atomicAdd(&g_cnt[dst], 1);
        }
    }
}

// ---------------- launch 1: single-pass decoupled-lookback scan ----------------
__global__ void k_scan() {
    __shared__ int sh[1024];
    __shared__ int s_base;
    int tid = threadIdx.x, bid = blockIdx.x;
    int i = bid * 1024 + tid;
    int v = 0;
    if (i < NN) {
        v = g_cnt[i];
        g_dis[i] = rsqrtf(g_deg[i] + 1.0f);
        g_cnt[i] = 0;
        g_deg[i] = 0.0f;
    }
    sh[tid] = v;
    __syncthreads();
    for (int ofs = 1; ofs < 1024; ofs <<= 1) {
        int t = (tid >= ofs) ? sh[tid - ofs] : 0;
        __syncthreads();
        sh[tid] += t;
        __syncthreads();
    }
    int incl = sh[tid];
    if (tid == 0) {
        int total = sh[1023];
        unsigned long long st =
            ((unsigned long long)(bid == 0 ? 2u : 1u) << 32) | (unsigned)total;
        atomicExch(&g_state[bid], st);
        int run = 0;
        if (bid > 0) {
            int p = bid - 1;
            while (true) {
                unsigned long long s;
                do { s = atomicAdd(&g_state[p], 0ULL); } while ((s >> 32) == 0);
                run += (int)(s & 0xffffffffu);
                if ((s >> 32) == 2u) break;
                p--;
            }
            atomicExch(&g_state[bid], (2ULL << 32) | (unsigned)(run + total));
        }
        s_base = run;
    }
    __syncthreads();
    if (i < NN) {
        int o = s_base + incl - v;
        g_off[i] = o;
        g_cur[i] = o;
    }
}

// ---------------- launch 2: fill CSR ----------------
__global__ void k_fill(const int* __restrict__ ei, const float* __restrict__ ew) {
    int e = blockIdx.x * blockDim.x + threadIdx.x;
    if (e < 256) g_state[e] = 0ULL;
    if (e == 0) g_off[NN] = EE;
    if (e < EE) {
        int src = ei[e];
        int dst = ei[EE + e];
        int pos = atomicAdd(&g_cur[dst], 1);
        float nrm = g_dis[src] * ew[e] * g_dis[dst];
        g_csr[pos] = make_int2(src, __float_as_int(nrm));
        g_eid[pos] = e;
    }
}

// ---------------- gather core v3: 8-chunk with subgroup shfl broadcast ----------------
// Accumulation order identical to the R11 4-chunk version: chain q gets edges
// congruent q mod 4 in sequence; remainder (<4) goes to a0.
__device__ __forceinline__ float4 agg_gather3(const float* __restrict__ x, int n,
                                              int sl, int sg) {
    int base = g_off[n];
    int cnt  = g_off[n + 1] - base;
    float dn = g_dis[n];
    float dd = dn * dn;
    const unsigned smask = 0xFFu << (sg << 3);
    const int sgb = sg << 3;
    const float4 xv = *reinterpret_cast<const float4*>(x + n * 32 + sl * 4);
    float4 a0, a1, a2, a3;
    a0.x = dd * xv.x; a0.y = dd * xv.y; a0.z = dd * xv.z; a0.w = dd * xv.w;
    a1 = make_float4(0.f, 0.f, 0.f, 0.f); a2 = a1; a3 = a1;
    int j = 0;
    for (; j + 8 <= cnt; j += 8) {
        int2 ec = g_csr[base + j + sl];   // lane sl holds edge j+sl of this subgroup's node
#pragma unroll
        for (int h = 0; h < 8; h += 4) {
            int   s0 = __shfl_sync(smask, ec.x, sgb + h);
            int   s1 = __shfl_sync(smask, ec.x, sgb + h + 1);
            float n0 = __int_as_float(__shfl_sync(smask, ec.y, sgb + h));
            float n1 = __int_as_float(__shfl_sync(smask, ec.y, sgb + h + 1));
            {
                const float4 x0 = *reinterpret_cast<const float4*>(x + s0 * 32 + sl * 4);
                const float4 x1 = *reinterpret_cast<const float4*>(x + s1 * 32 + sl * 4);
                a0.x += n0 * x0.x; a0.y += n0 * x0.y; a0.z += n0 * x0.z; a0.w += n0 * x0.w;
                a1.x += n1 * x1.x; a1.y += n1 * x1.y; a1.z += n1 * x1.z; a1.w += n1 * x1.w;
            }
            int   s2 = __shfl_sync(smask, ec.x, sgb + h + 2);
            int   s3 = __shfl_sync(smask, ec.x, sgb + h + 3);
            float n2 = __int_as_float(__shfl_sync(smask, ec.y, sgb + h + 2));
            float n3 = __int_as_float(__shfl_sync(smask, ec.y, sgb + h + 3));
            {
                const float4 x2 = *reinterpret_cast<const float4*>(x + s2 * 32 + sl * 4);
                const float4 x3 = *reinterpret_cast<const float4*>(x + s3 * 32 + sl * 4);
                a2.x += n2 * x2.x; a2.y += n2 * x2.y; a2.z += n2 * x2.z; a2.w += n2 * x2.w;
                a3.x += n3 * x3.x; a3.y += n3 * x3.y; a3.z += n3 * x3.z; a3.w += n3 * x3.w;
            }
        }
    }
    // 4-chunk fallback (scalar loads, R11 order)
    for (; j + 4 <= cnt; j += 4) {
        int2 c0 = g_csr[base + j], c1 = g_csr[base + j + 1];
        {
            const float4 x0 = *reinterpret_cast<const float4*>(x + c0.x * 32 + sl * 4);
            const float4 x1 = *reinterpret_cast<const float4*>(x + c1.x * 32 + sl * 4);
            float n0 = __int_as_float(c0.y), n1 = __int_as_float(c1.y);
            a0.x += n0 * x0.x; a0.y += n0 * x0.y; a0.z += n0 * x0.z; a0.w += n0 * x0.w;
            a1.x += n1 * x1.x; a1.y += n1 * x1.y; a1.z += n1 * x1.z; a1.w += n1 * x1.w;
        }
        int2 c2 = g_csr[base + j + 2], c3 = g_csr[base + j + 3];
        {
            const float4 x2 = *reinterpret_cast<const float4*>(x + c2.x * 32 + sl * 4);
            const float4 x3 = *reinterpret_cast<const float4*>(x + c3.x * 32 + sl * 4);
            float n2 = __int_as_float(c2.y), n3 = __int_as_float(c3.y);
            a2.x += n2 * x2.x; a2.y += n2 * x2.y; a2.z += n2 * x2.z; a2.w += n2 * x2.w;
            a3.x += n3 * x3.x; a3.y += n3 * x3.y; a3.z += n3 * x3.z; a3.w += n3 * x3.w;
        }
    }
    for (; j < cnt; j++) {
        int2 c = g_csr[base + j];
        const float4 xr = *reinterpret_cast<const float4*>(x + c.x * 32 + sl * 4);
        float nr = __int_as_float(c.y);
        a0.x += nr * xr.x; a0.y += nr * xr.y; a0.z += nr * xr.z; a0.w += nr * xr.w;
    }
    float4 r;
    r.x = a0.x + a1.x + a2.x + a3.x;
    r.y = a0.y + a1.y + a2.y + a3.y;
    r.z = a0.z + a1.z + a2.z + a3.z;
    r.w = a0.w + a1.w + a2.w + a3.w;
    return r;
}

__device__ __forceinline__ float4 epi_mm(float4 y, const float* Ws, int sg, int sl) {
    float4 acc = make_float4(0.f, 0.f, 0.f, 0.f);
#pragma unroll
    for (int k = 0; k < 32; k++) {
        float yk;
        if      ((k & 3) == 0) yk = y.x;
        else if ((k & 3) == 1) yk = y.y;
        else if ((k & 3) == 2) yk = y.z;
        else                   yk = y.w;
        yk = __shfl_sync(FULL, yk, (sg << 3) + (k >> 2));
        const float4 wk = *reinterpret_cast<const float4*>(Ws + k * 32 + sl * 4);
        acc.x += yk * wk.x; acc.y += yk * wk.y; acc.z += yk * wk.z; acc.w += yk * wk.w;
    }
    return acc;
}

// warp-wide deterministic reorder by eid: rank sort (cnt<=32), bitonic 33..64
__device__ __forceinline__ void sort_segment(int base, int cnt, int lane) {
    if (cnt <= 32) {
        int   eid = INT_MAX; int sv = 0; float wv = 0.f;
        if (lane < cnt) {
            int2 c = g_csr[base + lane];
            sv = c.x; wv = __int_as_float(c.y);
            eid = g_eid[base + lane];
        }
        int rank = 0;
#pragma unroll
        for (int j = 0; j < 32; j++) {
            int oe = __shfl_sync(FULL, eid, j);
            rank += (oe < eid) ? 1 : 0;
        }
        if (lane < cnt) g_csr[base + rank] = make_int2(sv, __float_as_int(wv));
    } else if (cnt <= 64) {
        int   e0 = INT_MAX, e1 = INT_MAX;
        int   s0v = 0, s1v = 0;
        float w0v = 0.f, w1v = 0.f;
        if (lane < cnt) {
            int2 c = g_csr[base + lane];
            s0v = c.x; w0v = __int_as_float(c.y); e0 = g_eid[base + lane];
        }
        if (lane + 32 < cnt) {
            int2 c = g_csr[base + lane + 32];
            s1v = c.x; w1v = __int_as_float(c.y); e1 = g_eid[base + lane + 32];
        }
        for (int k = 2; k <= 64; k <<= 1) {
            for (int j = k >> 1; j > 0; j >>= 1) {
                if (j == 32) {
                    if (e0 > e1) {
                        int te = e0; e0 = e1; e1 = te;
                        int ts = s0v; s0v = s1v; s1v = ts;
                        float tw = w0v; w0v = w1v; w1v = tw;
                    }
                } else {
                    int   oe0 = __shfl_xor_sync(FULL, e0, j);
                    int   os0 = __shfl_xor_sync(FULL, s0v, j);
                    float ow0 = __shfl_xor_sync(FULL, w0v, j);
                    int   oe1 = __shfl_xor_sync(FULL, e1, j);
                    int   os1 = __shfl_xor_sync(FULL, s1v, j);
                    float ow1 = __shfl_xor_sync(FULL, w1v, j);
                    bool lower = (lane & j) == 0;
                    bool asc0 = ((lane) & k) == 0;
                    bool asc1 = ((lane + 32) & k) == 0;
                    bool t0 = (lower == asc0) ? (oe0 < e0) : (oe0 > e0);
                    bool t1 = (lower == asc1) ? (oe1 < e1) : (oe1 > e1);
                    if (t0) { e0 = oe0; s0v = os0; w0v = ow0; }
                    if (t1) { e1 = oe1; s1v = os1; w1v = ow1; }
                }
            }
        }
        if (lane < cnt)      g_csr[base + lane]      = make_int2(s0v, __float_as_int(w0v));
        if (lane + 32 < cnt) g_csr[base + lane + 32] = make_int2(s1v, __float_as_int(w1v));
    }
}

// ---------------- launch 3 (PROFILED): layer 1 = rank-sort + vec gather + tanh + @W1 ----------------
__global__ void __launch_bounds__(256, 5) k_aggvs(
        const float* __restrict__ x, const float* __restrict__ W,
        const float* __restrict__ bias, float* __restrict__ outH,
        float* __restrict__ outXW) {
    __shared__ float Ws[32 * 32];
    for (int i = threadIdx.x; i < 32 * 32; i += blockDim.x) Ws[i] = W[i];
    __syncthreads();
    int lane = threadIdx.x & 31;
    int sl = lane & 7, sg = lane >> 3;
    int warp = (blockIdx.x * blockDim.x + threadIdx.x) >> 5;
    int nwarps = (gridDim.x * blockDim.x) >> 5;
    const float4 bl = *reinterpret_cast<const float4*>(bias + sl * 4);
    for (int n4 = warp * 4; n4 < NN; n4 += nwarps * 4) {
        for (int t = 0; t < 4; t++) {
            int nn = n4 + t;
            sort_segment(g_off[nn], g_off[nn + 1] - g_off[nn], lane);
        }
        __threadfence_block();
        __syncwarp();

        int n = n4 + sg;
        float4 r = agg_gather3(x, n, sl, sg);
        float4 y;
        y.x = tanhf(r.x + bl.x); y.y = tanhf(r.y + bl.y);
        y.z = tanhf(r.z + bl.z); y.w = tanhf(r.w + bl.w);
        *reinterpret_cast<float4*>(outH + n * 32 + sl * 4) = y;
        float4 acc = epi_mm(y, Ws, sg, sl);
        *reinterpret_cast<float4*>(outXW + n * 32 + sl * 4) = acc;
    }
}

// layer 2: vec gather + tanh + @W2
__global__ void __launch_bounds__(256, 5) k_aggv(
        const float* __restrict__ x, const float* __restrict__ W,
        const float* __restrict__ bias, float* __restrict__ outH,
        float* __restrict__ outXW) {
    __shared__ float Ws[32 * 32];
    for (int i = threadIdx.x; i < 32 * 32; i += blockDim.x) Ws[i] = W[i];
    __syncthreads();
    int lane = threadIdx.x & 31;
    int sl = lane & 7, sg = lane >> 3;
    int warp = (blockIdx.x * blockDim.x + threadIdx.x) >> 5;
    int nwarps = (gridDim.x * blockDim.x) >> 5;
    const float4 bl = *reinterpret_cast<const float4*>(bias + sl * 4);
    for (int n4 = warp * 4; n4 < NN; n4 += nwarps * 4) {
        int n = n4 + sg;
        float4 r = agg_gather3(x, n, sl, sg);
        float4 y;
        y.x = tanhf(r.x + bl.x); y.y = tanhf(r.y + bl.y);
        y.z = tanhf(r.z + bl.z); y.w = tanhf(r.w + bl.w);
        *reinterpret_cast<float4*>(outH + n * 32 + sl * 4) = y;
        float4 acc = epi_mm(y, Ws, sg, sl);
        *reinterpret_cast<float4*>(outXW + n * 32 + sl * 4) = acc;
    }
}

// layer 3: vec gather + tanh -> h3; scalar epilogue @W3 -> g_s
__global__ void __launch_bounds__(256, 5) k_aggvf(
        const float* __restrict__ x, const float* __restrict__ bias,
        const float* __restrict__ W3, float* __restrict__ outH) {
    int lane = threadIdx.x & 31;
    int sl = lane & 7, sg = lane >> 3;
    int warp = (blockIdx.x * blockDim.x + threadIdx.x) >> 5;
    int nwarps = (gridDim.x * blockDim.x) >> 5;
    const float4 bl  = *reinterpret_cast<const float4*>(bias + sl * 4);
    const float4 w3v = *reinterpret_cast<const float4*>(W3 + sl * 4);
    for (int n4 = warp * 4; n4 < NN; n4 += nwarps * 4) {
        int n = n4 + sg;
        float4 r = agg_gather3(x, n, sl, sg);
        float4 y;
        y.x = tanhf(r.x + bl.x); y.y = tanhf(r.y + bl.y);
        y.z = tanhf(r.z + bl.z); y.w = tanhf(r.w + bl.w);
        *reinterpret_cast<float4*>(outH + n * 32 + sl * 4) = y;
        float4 p;
        p.x = y.x * w3v.x; p.y = y.y * w3v.y; p.z = y.z * w3v.z; p.w = y.w * w3v.w;
        p.x += __shfl_down_sync(FULL, p.x, 4);
        p.y += __shfl_down_sync(FULL, p.y, 4);
        p.z += __shfl_down_sync(FULL, p.z, 4);
        p.w += __shfl_down_sync(FULL, p.w, 4);
        p.x += __shfl_down_sync(FULL, p.x, 2);
        p.y += __shfl_down_sync(FULL, p.y, 2);
        p.z += __shfl_down_sync(FULL, p.z, 2);
        p.w += __shfl_down_sync(FULL, p.w, 2);
        p.x += __shfl_down_sync(FULL, p.x, 1);
        p.y += __shfl_down_sync(FULL, p.y, 1);
        p.z += __shfl_down_sync(FULL, p.z, 1);
        p.w += __shfl_down_sync(FULL, p.w, 1);
        if (sl == 0) {
            float v4a = p.x + p.z;
            float v4b = p.y + p.w;
            g_s[n] = v4a + v4b;
        }
    }
}

// layer 4: scalar aggregate, subgroup-of-8 per node (4 nodes/warp)
__global__ void __launch_bounds__(256) k_agg1(const float* __restrict__ b3) {
    int lane = threadIdx.x & 31;
    int sl = lane & 7, sg = lane >> 3;
    int warp = (blockIdx.x * blockDim.x + threadIdx.x) >> 5;
    int nwarps = (gridDim.x * blockDim.x) >> 5;
    float b = b3[0];
    for (int n4 = warp * 4; n4 < NN; n4 += nwarps * 4) {
        int n = n4 + sg;
        int s0 = g_off[n], e0 = g_off[n + 1];
        float acc = 0.f;
        for (int i = s0 + sl; i < e0; i += 8) {
            int2 c = g_csr[i];
            acc += __int_as_float(c.y) * g_s[c.x];
        }
        acc += __shfl_down_sync(FULL, acc, 4);
        acc += __shfl_down_sync(FULL, acc, 2);
        acc += __shfl_down_sync(FULL, acc, 1);
        if (sl == 0) {
            float dn = g_dis[n];
            g_h4[n] = tanhf(acc + dn * dn * g_s[n] + b);
        }
    }
}

// ---------------- fused tail: 4 graphs per block ----------------
__global__ void k_tail(const float* __restrict__ c1W, const float* __restrict__ c1b,
                       const float* __restrict__ c2W, const float* __restrict__ c2b,
                       const float* __restrict__ l1W, const float* __restrict__ l1b,
                       const float* __restrict__ l2W, const float* __restrict__ l2b,
                       float* __restrict__ out) {
    __shared__ float s_vals[128];
    __shared__ int   s_idx[128];
    __shared__ float s_xs[KK * DD];
    __shared__ float s_w1[16 * DD];
    __shared__ float s_w2[2560];
    __shared__ float s_pool[16 * 30];
    __shared__ float s_flat[TG][832];
    __shared__ float s_red[TG][4];

    int t = threadIdx.x;
    int b0 = blockIdx.x * TG;

    for (int q = t; q < 16 * DD; q += 128) s_w1[q] = c1W[q];
    for (int q = t; q < 2560; q += 128) s_w2[q] = c2W[q];

    for (int g = 0; g < TG; g++) {
        int b = b0 + g;
        int g0 = b * NPG;

        float v = (t < NPG) ? g_h4[g0 + t] : -FLT_MAX;
        int   id = (t < NPG) ? t : 0x7fffffff;
        __syncthreads();
        s_vals[t] = v; s_idx[t] = id;
        __syncthreads();
        for (int k = 2; k <= 128; k <<= 1) {
            for (int j = k >> 1; j > 0; j >>= 1) {
                int ixj = t ^ j;
                if (ixj > t) {
                    float va = s_vals[t],  vb = s_vals[ixj];
                    int   ia = s_idx[t],   ib = s_idx[ixj];
                    bool before = (va > vb) || (va == vb && ia < ib);
                    bool up = ((t & k) == 0);
                    if (up ? !before : before) {
                        s_vals[t] = vb; s_vals[ixj] = va;
                        s_idx[t]  = ib; s_idx[ixj]  = ia;
                    }
                }
                __syncthreads();
            }
        }

        for (int q = t; q < KK * DD; q += 128) {
            int kk = q / DD, dd = q - kk * DD;
            int node = g0 + s_idx[kk];
            float val;
            if      (dd < 32) val = g_h1[node * 32 + dd];
            else if (dd < 64) val = g_h2[node * 32 + dd - 32];
            else if (dd < 96) val = g_h3[node * 32 + dd - 64];
            else              val = g_h4[node];
            s_xs[q] = val;
        }
        __syncthreads();

        // conv1 + relu + maxpool(2,2) fused
        for (int q = t; q < 16 * 30; q += 128) {
            int o = q / 30, p = q - o * 30;
            float accA = c1b[o], accB = c1b[o];
            int kA = 2 * p, kB = 2 * p + 1;
            for (int dd = 0; dd < DD; dd++) {
                float wv = s_w1[o * DD + dd];
                accA += s_xs[kA * DD + dd] * wv;
                accB += s_xs[kB * DD + dd] * wv;
            }
            s_pool[o * 30 + p] = fmaxf(fmaxf(accA, 0.f), fmaxf(accB, 0.f));
        }
        __syncthreads();

        for (int q = t; q < 832; q += 128) {
            int o = q / 26, p = q - o * 26;
            float acc = c2b[o];
            for (int i = 0; i < 16; i++) {
#pragma unroll
                for (int tt = 0; tt < 5; tt++)
                    acc += s_pool[i * 30 + p + tt] * s_w2[o * 80 + i * 5 + tt];
            }
            s_flat[g][o * 26 + p] = fmaxf(acc, 0.f);
        }
        __syncthreads();
    }

    // l1 for all TG graphs: single pass over l1W
    float acc0 = l1b[t], acc1 = acc0, acc2 = acc0, acc3 = acc0;
    for (int f = 0; f < 832; f++) {
        float wv = l1W[f * 128 + t];
        acc0 += s_flat[0][f] * wv;
        acc1 += s_flat[1][f] * wv;
        acc2 += s_flat[2][f] * wv;
        acc3 += s_flat[3][f] * wv;
    }
    float w2 = l2W[t];
    float y0 = fmaxf(acc0, 0.f) * w2;
    float y1 = fmaxf(acc1, 0.f) * w2;
    float y2 = fmaxf(acc2, 0.f) * w2;
    float y3 = fmaxf(acc3, 0.f) * w2;
#pragma unroll
    for (int o = 16; o > 0; o >>= 1) {
        y0 += __shfl_down_sync(FULL, y0, o);
        y1 += __shfl_down_sync(FULL, y1, o);
        y2 += __shfl_down_sync(FULL, y2, o);
        y3 += __shfl_down_sync(FULL, y3, o);
    }
    if ((t & 31) == 0) {
        s_red[0][t >> 5] = y0; s_red[1][t >> 5] = y1;
        s_red[2][t >> 5] = y2; s_red[3][t >> 5] = y3;
    }
    __syncthreads();
    if (t < TG)
        out[b0 + t] = s_red[t][0] + s_red[t][1] + s_red[t][2] + s_red[t][3] + l2b[0];
}

// ---------------- launch ----------------
extern "C" void kernel_launch(void* const* d_in, const int* in_sizes, int n_in,
                              void* d_out, int out_size) {
    const int*   z1    = (const int*)  d_in[0];
    const int*   z2    = (const int*)  d_in[1];
    const int*   w     = (const int*)  d_in[2];
    const int*   ei    = (const int*)  d_in[3];
    const float* ew    = (const float*)d_in[5];
    const float* emb_w = (const float*)d_in[6];
    const float* emb_z1= (const float*)d_in[7];
    const float* emb_z2= (const float*)d_in[8];
    const float* W0 = (const float*)d_in[9];
    const float* b0 = (const float*)d_in[10];
    const float* W1 = (const float*)d_in[11];
    const float* b1 = (const float*)d_in[12];
    const float* W2 = (const float*)d_in[13];
    const float* b2 = (const float*)d_in[14];
    const float* W3 = (const float*)d_in[15];
    const float* b3 = (const float*)d_in[16];
    const float* c1W = (const float*)d_in[17];
    const float* c1b = (const float*)d_in[18];
    const float* c2W = (const float*)d_in[19];
    const float* c2b = (const float*)d_in[20];
    const float* l1W = (const float*)d_in[21];
    const float* l1b = (const float*)d_in[22];
    const float* l2W = (const float*)d_in[23];
    const float* l2b = (const float*)d_in[24];
    float* out = (float*)d_out;

    const int nb_e = (EE + 255) / 256;
    const int nb_scan = (NN + 1023) / 1024;   // 196

    float *gx, *gy, *h1, *h2, *h3;
    cudaGetSymbolAddress((void**)&gx, g_x);
    cudaGetSymbolAddress((void**)&gy, g_y);
    cudaGetSymbolAddress((void**)&h1, g_h1);
    cudaGetSymbolAddress((void**)&h2, g_h2);
    cudaGetSymbolAddress((void**)&h3, g_h3);

    k_head <<<NBLK * 2, 256>>>(w, z1, z2, emb_w, emb_z1, emb_z2, W0, ei, ew);  // 0
    k_scan <<<nb_scan, 1024>>>();                                               // 1
    k_fill <<<nb_e, 256>>>(ei, ew);                                             // 2
    k_aggvs<<<AGRID, 256>>>(gx, W1, b0, h1, gy);                                // 3 <- profiled
    k_aggv <<<AGRID, 256>>>(gy, W2, b1, h2, gx);                                // 4
    k_aggvf<<<AGRID, 256>>>(gx, b2, W3, h3);                                    // 5
    k_agg1 <<<NBLK, 256>>>(b3);                                                 // 6
    k_tail <<<BB / TG, 128>>>(c1W, c1b, c2W, c2b, l1W, l1b, l2W, l2b, out);     // 7
}

// round 13
// speedup vs baseline: 1.5060x; 1.5060x over previous
#include <cuda_runtime.h>
#include <cuda_bf16.h>
#include <cfloat>
#include <math.h>
#include <limits.h>

#define NN 200000
#define EE 3200000
#define BB 2000
#define NPG 100
#define KK 60
#define DD 97
#define NBLK 1184
#define AGRID 1184
#define TG 4
#define FULL 0xffffffffu

// ---------------- device scratch ----------------
__device__ float g_deg[NN];          // edge-weight sum only; reset in k_scan
__device__ float g_dis[NN];
__device__ int   g_cnt[NN];          // zero-init; reset in k_scan
__device__ int   g_off[NN + 1];
__device__ int   g_cur[NN];
__device__ unsigned long long g_state[256];  // lookback; reset in k_fill
__device__ int2  g_csr[EE];          // .x = src, .y = norm bits
__device__ int   g_eid[EE];
__device__ float g_x [NN * 32];
__device__ float g_y [NN * 32];
__device__ float g_h1[NN * 32];
__device__ float g_h2[NN * 32];
__device__ float g_h3[NN * 32];
__device__ float g_s [NN];
__device__ float g_h4[NN];

// ---------------- launch 0: mm0 (node blocks, float4 subgroup) + hist (edge blocks) ----------------
__global__ void k_head(const int* __restrict__ w, const int* __restrict__ z1,
                       const int* __restrict__ z2,
                       const float* __restrict__ emb_w, const float* __restrict__ emb_z1,
                       const float* __restrict__ emb_z2, const float* __restrict__ W0,
                       const int* __restrict__ ei, const float* __restrict__ ew) {
    if (blockIdx.x < NBLK) {
        __shared__ float Ws[96 * 32];
        for (int i = threadIdx.x; i < 96 * 32; i += blockDim.x) Ws[i] = W0[i];
        __syncthreads();
        int lane = threadIdx.x & 31;
        int sl = lane & 7, sg = lane >> 3;
        int warp = (blockIdx.x * blockDim.x + threadIdx.x) >> 5;
        const int nwarps = NBLK * 8;
        for (int n4 = warp * 4; n4 < NN; n4 += nwarps * 4) {
            int n = n4 + sg;
            const float4 r0 = *reinterpret_cast<const float4*>(emb_w  + w [n] * 32 + sl * 4);
            const float4 r1 = *reinterpret_cast<const float4*>(emb_z1 + z1[n] * 32 + sl * 4);
            const float4 r2 = *reinterpret_cast<const float4*>(emb_z2 + z2[n] * 32 + sl * 4);
            float4 acc = make_float4(0.f, 0.f, 0.f, 0.f);
#pragma unroll
            for (int k = 0; k < 32; k++) {
                float yk;
                if      ((k & 3) == 0) yk = r0.x;
                else if ((k & 3) == 1) yk = r0.y;
                else if ((k & 3) == 2) yk = r0.z;
                else                   yk = r0.w;
                yk = __shfl_sync(FULL, yk, (sg << 3) + (k >> 2));
                const float4 wk = *reinterpret_cast<const float4*>(Ws + k * 32 + sl * 4);
                acc.x += yk * wk.x; acc.y += yk * wk.y; acc.z += yk * wk.z; acc.w += yk * wk.w;
            }
#pragma unroll
            for (int k = 0; k < 32; k++) {
                float yk;
                if      ((k & 3) == 0) yk = r1.x;
                else if ((k & 3) == 1) yk = r1.y;
                else if ((k & 3) == 2) yk = r1.z;
                else                   yk = r1.w;
                yk = __shfl_sync(FULL, yk, (sg << 3) + (k >> 2));
                const float4 wk = *reinterpret_cast<const float4*>(Ws + (32 + k) * 32 + sl * 4);
                acc.x += yk * wk.x; acc.y += yk * wk.y; acc.z += yk * wk.z; acc.w += yk * wk.w;
            }
#pragma unroll
            for (int k = 0; k < 32; k++) {
                float yk;
                if      ((k & 3) == 0) yk = r2.x;
                else if ((k & 3) == 1) yk = r2.y;
                else if ((k & 3) == 2) yk = r2.z;
                else                   yk = r2.w;
                yk = __shfl_sync(FULL, yk, (sg << 3) + (k >> 2));
                const float4 wk = *reinterpret_cast<const float4*>(Ws + (64 + k) * 32 + sl * 4);
                acc.x += yk * wk.x; acc.y += yk * wk.y; acc.z += yk * wk.z; acc.w += yk * wk.w;
            }
            *reinterpret_cast<float4*>(g_x + n * 32 + sl * 4) = acc;
        }
    } else {
        int tid = (blockIdx.x - NBLK) * blockDim.x + threadIdx.x;
        const int nthr = NBLK * 256;
        for (int e = tid; e < EE; e += nthr) {
            int dst = ei[EE + e];
            atomicAdd(&g_deg[dst], ew[e]);
            atomicAdd(&g_cnt[dst], 1);
        }
    }
}

// ---------------- launch 1: single-pass decoupled-lookback scan ----------------
__global__ void k_scan() {
    __shared__ int sh[1024];
    __shared__ int s_base;
    int tid = threadIdx.x, bid = blockIdx.x;
    int i = bid * 1024 + tid;
    int v = 0;
    if (i < NN) {
        v = g_cnt[i];
        g_dis[i] = rsqrtf(g_deg[i] + 1.0f);
        g_cnt[i] = 0;
        g_deg[i] = 0.0f;
    }
    sh[tid] = v;
    __syncthreads();
    for (int ofs = 1; ofs < 1024; ofs <<= 1) {
        int t = (tid >= ofs) ? sh[tid - ofs] : 0;
        __syncthreads();
        sh[tid] += t;
        __syncthreads();
    }
    int incl = sh[tid];
    if (tid == 0) {
        int total = sh[1023];
        unsigned long long st =
            ((unsigned long long)(bid == 0 ? 2u : 1u) << 32) | (unsigned)total;
        atomicExch(&g_state[bid], st);
        int run = 0;
        if (bid > 0) {
            int p = bid - 1;
            while (true) {
                unsigned long long s;
                do { s = atomicAdd(&g_state[p], 0ULL); } while ((s >> 32) == 0);
                run += (int)(s & 0xffffffffu);
                if ((s >> 32) == 2u) break;
                p--;
            }
            atomicExch(&g_state[bid], (2ULL << 32) | (unsigned)(run + total));
        }
        s_base = run;
    }
    __syncthreads();
    if (i < NN) {
        int o = s_base + incl - v;
        g_off[i] = o;
        g_cur[i] = o;
    }
}

// ---------------- launch 2: fill CSR ----------------
__global__ void k_fill(const int* __restrict__ ei, const float* __restrict__ ew) {
    int e = blockIdx.x * blockDim.x + threadIdx.x;
    if (e < 256) g_state[e] = 0ULL;
    if (e == 0) g_off[NN] = EE;
    if (e < EE) {
        int src = ei[e];
        int dst = ei[EE + e];
        int pos = atomicAdd(&g_cur[dst], 1);
        float nrm = g_dis[src] * ew[e] * g_dis[dst];
        g_csr[pos] = make_int2(src, __float_as_int(nrm));
        g_eid[pos] = e;
    }
}

// ---------------- gather core (R11-proven: lane-local broadcast csr loads) ----------------
__device__ __forceinline__ float4 agg_gather2(const float* __restrict__ x, int n, int sl) {
    int base = g_off[n];
    int cnt  = g_off[n + 1] - base;
    float dn = g_dis[n];
    float dd = dn * dn;
    const float4 xv = *reinterpret_cast<const float4*>(x + n * 32 + sl * 4);
    float4 a0, a1, a2, a3;
    a0.x = dd * xv.x; a0.y = dd * xv.y; a0.z = dd * xv.z; a0.w = dd * xv.w;
    a1 = make_float4(0.f, 0.f, 0.f, 0.f); a2 = a1; a3 = a1;
    int j = 0;
    for (; j + 4 <= cnt; j += 4) {
        int2 c0 = g_csr[base + j], c1 = g_csr[base + j + 1];
        {
            const float4 x0 = *reinterpret_cast<const float4*>(x + c0.x * 32 + sl * 4);
            const float4 x1 = *reinterpret_cast<const float4*>(x + c1.x * 32 + sl * 4);
            float n0 = __int_as_float(c0.y), n1 = __int_as_float(c1.y);
            a0.x += n0 * x0.x; a0.y += n0 * x0.y; a0.z += n0 * x0.z; a0.w += n0 * x0.w;
            a1.x += n1 * x1.x; a1.y += n1 * x1.y; a1.z += n1 * x1.z; a1.w += n1 * x1.w;
        }
        int2 c2 = g_csr[base + j + 2], c3 = g_csr[base + j + 3];
        {
            const float4 x2 = *reinterpret_cast<const float4*>(x + c2.x * 32 + sl * 4);
            const float4 x3 = *reinterpret_cast<const float4*>(x + c3.x * 32 + sl * 4);
            float n2 = __int_as_float(c2.y), n3 = __int_as_float(c3.y);
            a2.x += n2 * x2.x; a2.y += n2 * x2.y; a2.z += n2 * x2.z; a2.w += n2 * x2.w;
            a3.x += n3 * x3.x; a3.y += n3 * x3.y; a3.z += n3 * x3.z; a3.w += n3 * x3.w;
        }
    }
    for (; j < cnt; j++) {
        int2 c = g_csr[base + j];
        const float4 xr = *reinterpret_cast<const float4*>(x + c.x * 32 + sl * 4);
        float nr = __int_as_float(c.y);
        a0.x += nr * xr.x; a0.y += nr * xr.y; a0.z += nr * xr.z; a0.w += nr * xr.w;
    }
    float4 r;
    r.x = a0.x + a1.x + a2.x + a3.x;
    r.y = a0.y + a1.y + a2.y + a3.y;
    r.z = a0.z + a1.z + a2.z + a3.z;
    r.w = a0.w + a1.w + a2.w + a3.w;
    return r;
}

__device__ __forceinline__ float4 epi_mm(float4 y, const float* Ws, int sg, int sl) {
    float4 acc = make_float4(0.f, 0.f, 0.f, 0.f);
#pragma unroll
    for (int k = 0; k < 32; k++) {
        float yk;
        if      ((k & 3) == 0) yk = y.x;
        else if ((k & 3) == 1) yk = y.y;
        else if ((k & 3) == 2) yk = y.z;
        else                   yk = y.w;
        yk = __shfl_sync(FULL, yk, (sg << 3) + (k >> 2));
        const float4 wk = *reinterpret_cast<const float4*>(Ws + k * 32 + sl * 4);
        acc.x += yk * wk.x; acc.y += yk * wk.y; acc.z += yk * wk.z; acc.w += yk * wk.w;
    }
    return acc;
}

// warp-wide deterministic reorder by eid: rank sort (cnt<=32), bitonic 33..64
__device__ __forceinline__ void sort_segment(int base, int cnt, int lane) {
    if (cnt <= 32) {
        int   eid = INT_MAX; int sv = 0; float wv = 0.f;
        if (lane < cnt) {
            int2 c = g_csr[base + lane];
            sv = c.x; wv = __int_as_float(c.y);
            eid = g_eid[base + lane];
        }
        int rank = 0;
#pragma unroll
        for (int j = 0; j < 32; j++) {
            int oe = __shfl_sync(FULL, eid, j);
            rank += (oe < eid) ? 1 : 0;
        }
        if (lane < cnt) g_csr[base + rank] = make_int2(sv, __float_as_int(wv));
    } else if (cnt <= 64) {
        int   e0 = INT_MAX, e1 = INT_MAX;
        int   s0v = 0, s1v = 0;
        float w0v = 0.f, w1v = 0.f;
        if (lane < cnt) {
            int2 c = g_csr[base + lane];
            s0v = c.x; w0v = __int_as_float(c.y); e0 = g_eid[base + lane];
        }
        if (lane + 32 < cnt) {
            int2 c = g_csr[base + lane + 32];
            s1v = c.x; w1v = __int_as_float(c.y); e1 = g_eid[base + lane + 32];
        }
        for (int k = 2; k <= 64; k <<= 1) {
            for (int j = k >> 1; j > 0; j >>= 1) {
                if (j == 32) {
                    if (e0 > e1) {
                        int te = e0; e0 = e1; e1 = te;
                        int ts = s0v; s0v = s1v; s1v = ts;
                        float tw = w0v; w0v = w1v; w1v = tw;
                    }
                } else {
                    int   oe0 = __shfl_xor_sync(FULL, e0, j);
                    int   os0 = __shfl_xor_sync(FULL, s0v, j);
                    float ow0 = __shfl_xor_sync(FULL, w0v, j);
                    int   oe1 = __shfl_xor_sync(FULL, e1, j);
                    int   os1 = __shfl_xor_sync(FULL, s1v, j);
                    float ow1 = __shfl_xor_sync(FULL, w1v, j);
                    bool lower = (lane & j) == 0;
                    bool asc0 = ((lane) & k) == 0;
                    bool asc1 = ((lane + 32) & k) == 0;
                    bool t0 = (lower == asc0) ? (oe0 < e0) : (oe0 > e0);
                    bool t1 = (lower == asc1) ? (oe1 < e1) : (oe1 > e1);
                    if (t0) { e0 = oe0; s0v = os0; w0v = ow0; }
                    if (t1) { e1 = oe1; s1v = os1; w1v = ow1; }
                }
            }
        }
        if (lane < cnt)      g_csr[base + lane]      = make_int2(s0v, __float_as_int(w0v));
        if (lane + 32 < cnt) g_csr[base + lane + 32] = make_int2(s1v, __float_as_int(w1v));
    }
}

// ---------------- launch 3 (PROFILED): layer 1 = rank-sort + vec gather + tanh + @W1 ----------------
__global__ void __launch_bounds__(256, 5) k_aggvs(
        const float* __restrict__ x, const float* __restrict__ W,
        const float* __restrict__ bias, float* __restrict__ outH,
        float* __restrict__ outXW) {
    __shared__ float Ws[32 * 32];
    for (int i = threadIdx.x; i < 32 * 32; i += blockDim.x) Ws[i] = W[i];
    __syncthreads();
    int lane = threadIdx.x & 31;
    int sl = lane & 7, sg = lane >> 3;
    int warp = (blockIdx.x * blockDim.x + threadIdx.x) >> 5;
    int nwarps = (gridDim.x * blockDim.x) >> 5;
    const float4 bl = *reinterpret_cast<const float4*>(bias + sl * 4);
    for (int n4 = warp * 4; n4 < NN; n4 += nwarps * 4) {
        for (int t = 0; t < 4; t++) {
            int nn = n4 + t;
            sort_segment(g_off[nn], g_off[nn + 1] - g_off[nn], lane);
        }
        __threadfence_block();
        __syncwarp();

        int n = n4 + sg;
        float4 r = agg_gather2(x, n, sl);
        float4 y;
        y.x = tanhf(r.x + bl.x); y.y = tanhf(r.y + bl.y);
        y.z = tanhf(r.z + bl.z); y.w = tanhf(r.w + bl.w);
        *reinterpret_cast<float4*>(outH + n * 32 + sl * 4) = y;
        float4 acc = epi_mm(y, Ws, sg, sl);
        *reinterpret_cast<float4*>(outXW + n * 32 + sl * 4) = acc;
    }
}

// layer 2: vec gather + tanh + @W2 (occupancy-6 experiment)
__global__ void __launch_bounds__(256, 6) k_aggv(
        const float* __restrict__ x, const float* __restrict__ W,
        const float* __restrict__ bias, float* __restrict__ outH,
        float* __restrict__ outXW) {
    __shared__ float Ws[32 * 32];
    for (int i = threadIdx.x; i < 32 * 32; i += blockDim.x) Ws[i] = W[i];
    __syncthreads();
    int lane = threadIdx.x & 31;
    int sl = lane & 7, sg = lane >> 3;
    int warp = (blockIdx.x * blockDim.x + threadIdx.x) >> 5;
    int nwarps = (gridDim.x * blockDim.x) >> 5;
    const float4 bl = *reinterpret_cast<const float4*>(bias + sl * 4);
    for (int n4 = warp * 4; n4 < NN; n4 += nwarps * 4) {
        int n = n4 + sg;
        float4 r = agg_gather2(x, n, sl);
        float4 y;
        y.x = tanhf(r.x + bl.x); y.y = tanhf(r.y + bl.y);
        y.z = tanhf(r.z + bl.z); y.w = tanhf(r.w + bl.w);
        *reinterpret_cast<float4*>(outH + n * 32 + sl * 4) = y;
        float4 acc = epi_mm(y, Ws, sg, sl);
        *reinterpret_cast<float4*>(outXW + n * 32 + sl * 4) = acc;
    }
}

// layer 3: vec gather + tanh -> h3; scalar epilogue @W3 -> g_s (occupancy-6 experiment)
__global__ void __launch_bounds__(256, 6) k_aggvf(
        const float* __restrict__ x, const float* __restrict__ bias,
        const float* __restrict__ W3, float* __restrict__ outH) {
    int lane = threadIdx.x & 31;
    int sl = lane & 7, sg = lane >> 3;
    int warp = (blockIdx.x * blockDim.x + threadIdx.x) >> 5;
    int nwarps = (gridDim.x * blockDim.x) >> 5;
    const float4 bl  = *reinterpret_cast<const float4*>(bias + sl * 4);
    const float4 w3v = *reinterpret_cast<const float4*>(W3 + sl * 4);
    for (int n4 = warp * 4; n4 < NN; n4 += nwarps * 4) {
        int n = n4 + sg;
        float4 r = agg_gather2(x, n, sl);
        float4 y;
        y.x = tanhf(r.x + bl.x); y.y = tanhf(r.y + bl.y);
        y.z = tanhf(r.z + bl.z); y.w = tanhf(r.w + bl.w);
        *reinterpret_cast<float4*>(outH + n * 32 + sl * 4) = y;
        float4 p;
        p.x = y.x * w3v.x; p.y = y.y * w3v.y; p.z = y.z * w3v.z; p.w = y.w * w3v.w;
        p.x += __shfl_down_sync(FULL, p.x, 4);
        p.y += __shfl_down_sync(FULL, p.y, 4);
        p.z += __shfl_down_sync(FULL, p.z, 4);
        p.w += __shfl_down_sync(FULL, p.w, 4);
        p.x += __shfl_down_sync(FULL, p.x, 2);
        p.y += __shfl_down_sync(FULL, p.y, 2);
        p.z += __shfl_down_sync(FULL, p.z, 2);
        p.w += __shfl_down_sync(FULL, p.w, 2);
        p.x += __shfl_down_sync(FULL, p.x, 1);
        p.y += __shfl_down_sync(FULL, p.y, 1);
        p.z += __shfl_down_sync(FULL, p.z, 1);
        p.w += __shfl_down_sync(FULL, p.w, 1);
        if (sl == 0) {
            float v4a = p.x + p.z;
            float v4b = p.y + p.w;
            g_s[n] = v4a + v4b;
        }
    }
}

// layer 4: scalar aggregate, subgroup-of-8 per node (4 nodes/warp)
__global__ void __launch_bounds__(256) k_agg1(const float* __restrict__ b3) {
    int lane = threadIdx.x & 31;
    int sl = lane & 7, sg = lane >> 3;
    int warp = (blockIdx.x * blockDim.x + threadIdx.x) >> 5;
    int nwarps = (gridDim.x * blockDim.x) >> 5;
    float b = b3[0];
    for (int n4 = warp * 4; n4 < NN; n4 += nwarps * 4) {
        int n = n4 + sg;
        int s0 = g_off[n], e0 = g_off[n + 1];
        float acc = 0.f;
        for (int i = s0 + sl; i < e0; i += 8) {
            int2 c = g_csr[i];
            acc += __int_as_float(c.y) * g_s[c.x];
        }
        acc += __shfl_down_sync(FULL, acc, 4);
        acc += __shfl_down_sync(FULL, acc, 2);
        acc += __shfl_down_sync(FULL, acc, 1);
        if (sl == 0) {
            float dn = g_dis[n];
            g_h4[n] = tanhf(acc + dn * dn * g_s[n] + b);
        }
    }
}

// ---------------- fused tail: 4 graphs per block ----------------
__global__ void k_tail(const float* __restrict__ c1W, const float* __restrict__ c1b,
                       const float* __restrict__ c2W, const float* __restrict__ c2b,
                       const float* __restrict__ l1W, const float* __restrict__ l1b,
                       const float* __restrict__ l2W, const float* __restrict__ l2b,
                       float* __restrict__ out) {
    __shared__ float s_vals[128];
    __shared__ int   s_idx[128];
    __shared__ float s_xs[KK * DD];
    __shared__ float s_w1[16 * DD];
    __shared__ float s_w2[2560];
    __shared__ float s_pool[16 * 30];
    __shared__ float s_flat[TG][832];
    __shared__ float s_red[TG][4];

    int t = threadIdx.x;
    int b0 = blockIdx.x * TG;

    for (int q = t; q < 16 * DD; q += 128) s_w1[q] = c1W[q];
    for (int q = t; q < 2560; q += 128) s_w2[q] = c2W[q];

    for (int g = 0; g < TG; g++) {
        int b = b0 + g;
        int g0 = b * NPG;

        float v = (t < NPG) ? g_h4[g0 + t] : -FLT_MAX;
        int   id = (t < NPG) ? t : 0x7fffffff;
        __syncthreads();
        s_vals[t] = v; s_idx[t] = id;
        __syncthreads();
        for (int k = 2; k <= 128; k <<= 1) {
            for (int j = k >> 1; j > 0; j >>= 1) {
                int ixj = t ^ j;
                if (ixj > t) {
                    float va = s_vals[t],  vb = s_vals[ixj];
                    int   ia = s_idx[t],   ib = s_idx[ixj];
                    bool before = (va > vb) || (va == vb && ia < ib);
                    bool up = ((t & k) == 0);
                    if (up ? !before : before) {
                        s_vals[t] = vb; s_vals[ixj] = va;
                        s_idx[t]  = ib; s_idx[ixj]  = ia;
                    }
                }
                __syncthreads();
            }
        }

        for (int q = t; q < KK * DD; q += 128) {
            int kk = q / DD, dd = q - kk * DD;
            int node = g0 + s_idx[kk];
            float val;
            if      (dd < 32) val = g_h1[node * 32 + dd];
            else if (dd < 64) val = g_h2[node * 32 + dd - 32];
            else if (dd < 96) val = g_h3[node * 32 + dd - 64];
            else              val = g_h4[node];
            s_xs[q] = val;
        }
        __syncthreads();

        // conv1 + relu + maxpool(2,2) fused
        for (int q = t; q < 16 * 30; q += 128) {
            int o = q / 30, p = q - o * 30;
            float accA = c1b[o], accB = c1b[o];
            int kA = 2 * p, kB = 2 * p + 1;
            for (int dd = 0; dd < DD; dd++) {
                float wv = s_w1[o * DD + dd];
                accA += s_xs[kA * DD + dd] * wv;
                accB += s_xs[kB * DD + dd] * wv;
            }
            s_pool[o * 30 + p] = fmaxf(fmaxf(accA, 0.f), fmaxf(accB, 0.f));
        }
        __syncthreads();

        for (int q = t; q < 832; q += 128) {
            int o = q / 26, p = q - o * 26;
            float acc = c2b[o];
            for (int i = 0; i < 16; i++) {
#pragma unroll
                for (int tt = 0; tt < 5; tt++)
                    acc += s_pool[i * 30 + p + tt] * s_w2[o * 80 + i * 5 + tt];
            }
            s_flat[g][o * 26 + p] = fmaxf(acc, 0.f);
        }
        __syncthreads();
    }

    // l1 for all TG graphs: single pass over l1W
    float acc0 = l1b[t], acc1 = acc0, acc2 = acc0, acc3 = acc0;
    for (int f = 0; f < 832; f++) {
        float wv = l1W[f * 128 + t];
        acc0 += s_flat[0][f] * wv;
        acc1 += s_flat[1][f] * wv;
        acc2 += s_flat[2][f] * wv;
        acc3 += s_flat[3][f] * wv;
    }
    float w2 = l2W[t];
    float y0 = fmaxf(acc0, 0.f) * w2;
    float y1 = fmaxf(acc1, 0.f) * w2;
    float y2 = fmaxf(acc2, 0.f) * w2;
    float y3 = fmaxf(acc3, 0.f) * w2;
#pragma unroll
    for (int o = 16; o > 0; o >>= 1) {
        y0 += __shfl_down_sync(FULL, y0, o);
        y1 += __shfl_down_sync(FULL, y1, o);
        y2 += __shfl_down_sync(FULL, y2, o);
        y3 += __shfl_down_sync(FULL, y3, o);
    }
    if ((t & 31) == 0) {
        s_red[0][t >> 5] = y0; s_red[1][t >> 5] = y1;
        s_red[2][t >> 5] = y2; s_red[3][t >> 5] = y3;
    }
    __syncthreads();
    if (t < TG)
        out[b0 + t] = s_red[t][0] + s_red[t][1] + s_red[t][2] + s_red[t][3] + l2b[0];
}

// ---------------- launch ----------------
extern "C" void kernel_launch(void* const* d_in, const int* in_sizes, int n_in,
                              void* d_out, int out_size) {
    const int*   z1    = (const int*)  d_in[0];
    const int*   z2    = (const int*)  d_in[1];
    const int*   w     = (const int*)  d_in[2];
    const int*   ei    = (const int*)  d_in[3];
    const float* ew    = (const float*)d_in[5];
    const float* emb_w = (const float*)d_in[6];
    const float* emb_z1= (const float*)d_in[7];
    const float* emb_z2= (const float*)d_in[8];
    const float* W0 = (const float*)d_in[9];
    const float* b0 = (const float*)d_in[10];
    const float* W1 = (const float*)d_in[11];
    const float* b1 = (const float*)d_in[12];
    const float* W2 = (const float*)d_in[13];
    const float* b2 = (const float*)d_in[14];
    const float* W3 = (const float*)d_in[15];
    const float* b3 = (const float*)d_in[16];
    const float* c1W = (const float*)d_in[17];
    const float* c1b = (const float*)d_in[18];
    const float* c2W = (const float*)d_in[19];
    const float* c2b = (const float*)d_in[20];
    const float* l1W = (const float*)d_in[21];
    const float* l1b = (const float*)d_in[22];
    const float* l2W = (const float*)d_in[23];
    const float* l2b = (const float*)d_in[24];
    float* out = (float*)d_out;

    const int nb_e = (EE + 255) / 256;
    const int nb_scan = (NN + 1023) / 1024;   // 196

    float *gx, *gy, *h1, *h2, *h3;
    cudaGetSymbolAddress((void**)&gx, g_x);
    cudaGetSymbolAddress((void**)&gy, g_y);
    cudaGetSymbolAddress((void**)&h1, g_h1);
    cudaGetSymbolAddress((void**)&h2, g_h2);
    cudaGetSymbolAddress((void**)&h3, g_h3);

    k_head <<<NBLK * 2, 256>>>(w, z1, z2, emb_w, emb_z1, emb_z2, W0, ei, ew);  // 0
    k_scan <<<nb_scan, 1024>>>();                                               // 1
    k_fill <<<nb_e, 256>>>(ei, ew);                                             // 2
    k_aggvs<<<AGRID, 256>>>(gx, W1, b0, h1, gy);                                // 3 <- profiled
    k_aggv <<<AGRID, 256>>>(gy, W2, b1, h2, gx);                                // 4
    k_aggvf<<<AGRID, 256>>>(gx, b2, W3, h3);                                    // 5
    k_agg1 <<<NBLK, 256>>>(b3);                                                 // 6
    k_tail <<<BB / TG, 128>>>(c1W, c1b, c2W, c2b, l1W, l1b, l2W, l2b, out);     // 7
}